// round 1
// baseline (speedup 1.0000x reference)
#include <cuda_runtime.h>

#define CH 256
#define QEPS 1e-4f

// Scratch (no allocations allowed): 14 reduction slots, 4x4 fused matrix M, means.
__device__ float g_sums[14 * CH];
__device__ float g_M[16 * CH];
__device__ float g_mu[4 * CH];

// ---------------------------------------------------------------------------
// Kernel 0: zero the reduction scratch (graph replays must be deterministic).
// ---------------------------------------------------------------------------
__global__ void k_zero() {
    int i = blockIdx.x * blockDim.x + threadIdx.x;
    if (i < 14 * CH) g_sums[i] = 0.0f;
}

// ---------------------------------------------------------------------------
// Kernel 1: per-channel sums and product-sums.
// thread c = channel (0..255), block handles `rowsPerBlock` consecutive
// spatial rows. Fully coalesced 32-bit loads, 14 register accumulators,
// 14 atomicAdds per thread at the end.
// ---------------------------------------------------------------------------
__global__ void __launch_bounds__(CH) k_reduce(const float* __restrict__ x,
                                               int S, int rowsPerBlock) {
    const int c = threadIdx.x;
    long long s0 = (long long)blockIdx.x * rowsPerBlock;
    if (s0 >= S) return;
    int nrows = rowsPerBlock;
    if (s0 + nrows > S) nrows = (int)(S - s0);

    const long long CS = (long long)S * CH;
    const float* b = x + s0 * CH + c;

    float sm0 = 0.f, sm1 = 0.f, sm2 = 0.f, sm3 = 0.f;
    float p00 = 0.f, p01 = 0.f, p02 = 0.f, p03 = 0.f;
    float p11 = 0.f, p12 = 0.f, p13 = 0.f;
    float p22 = 0.f, p23 = 0.f, p33 = 0.f;

#pragma unroll 2
    for (int r = 0; r < nrows; ++r) {
        long long off = (long long)r * CH;
        float x0 = __ldg(b + off);
        float x1 = __ldg(b + CS + off);
        float x2 = __ldg(b + 2 * CS + off);
        float x3 = __ldg(b + 3 * CS + off);
        sm0 += x0; sm1 += x1; sm2 += x2; sm3 += x3;
        p00 += x0 * x0; p01 += x0 * x1; p02 += x0 * x2; p03 += x0 * x3;
        p11 += x1 * x1; p12 += x1 * x2; p13 += x1 * x3;
        p22 += x2 * x2; p23 += x2 * x3;
        p33 += x3 * x3;
    }

    atomicAdd(&g_sums[0 * CH + c], sm0);
    atomicAdd(&g_sums[1 * CH + c], sm1);
    atomicAdd(&g_sums[2 * CH + c], sm2);
    atomicAdd(&g_sums[3 * CH + c], sm3);
    atomicAdd(&g_sums[4 * CH + c], p00);   // rr
    atomicAdd(&g_sums[5 * CH + c], p01);   // ri
    atomicAdd(&g_sums[6 * CH + c], p02);   // rj
    atomicAdd(&g_sums[7 * CH + c], p03);   // rk
    atomicAdd(&g_sums[8 * CH + c], p11);   // ii
    atomicAdd(&g_sums[9 * CH + c], p12);   // ij
    atomicAdd(&g_sums[10 * CH + c], p13);  // ik
    atomicAdd(&g_sums[11 * CH + c], p22);  // jj
    atomicAdd(&g_sums[12 * CH + c], p23);  // jk
    atomicAdd(&g_sums[13 * CH + c], p33);  // kk
}

// ---------------------------------------------------------------------------
// Kernel 2: per-channel stats -> whitening matrix -> M = G @ W.
// One block, thread = channel. Mirrors _whitening_matrix exactly.
// ---------------------------------------------------------------------------
__global__ void k_stats(const float* __restrict__ gamma, int S) {
    const int c = threadIdx.x;
    const float invN = 1.0f / (float)S;

    float mu[4];
#pragma unroll
    for (int p = 0; p < 4; ++p) mu[p] = g_sums[p * CH + c] * invN;

    // cov entries: 0 rr,1 ri,2 rj,3 rk,4 ii,5 ij,6 ik,7 jj,8 jk,9 kk
    const int ta[10] = {0, 0, 0, 0, 1, 1, 1, 2, 2, 3};
    const int tb[10] = {0, 1, 2, 3, 1, 2, 3, 2, 3, 3};
    float v[10];
#pragma unroll
    for (int i = 0; i < 10; ++i) {
        v[i] = g_sums[(4 + i) * CH + c] * invN - mu[ta[i]] * mu[tb[i]];
        if (ta[i] == tb[i]) v[i] += QEPS;
    }

    float wrr = sqrtf(v[0]);
    float wri = v[1] / wrr;
    float wii = sqrtf(v[4] - wri * wri);
    float wrj = v[2] / wrr;
    float wij = (v[5] - wri * wrj) / wii;
    float wjj = sqrtf(v[7] - (wij * wij + wrj * wrj));
    float wrk = v[3] / wrr;
    float wik = (v[6] - wri * wrk) / wii;
    float wjk = (v[8] - (wij * wik + wrj * wrk)) / wjj;
    float wkk = sqrtf(v[9] - (wjk * wjk + wik * wik + wrk * wrk));

    float orr = 1.0f / wrr, oii = 1.0f / wii, ojj = 1.0f / wjj, okk = 1.0f / wkk;
    float ori = -(wri * orr) / wii;
    float orj = -(wrj * orr + wij * ori) / wjj;
    float ork = -(wrk * orr + wik * ori + wjk * orj) / wkk;
    float oij = -(wij * oii) / wjj;
    float oik = -(wik * oii + wjk * oij) / wkk;
    float ojk = -(wjk * ojj) / wkk;

    float W[4][4] = {{orr, ori, orj, ork},
                     {ori, oii, oij, oik},
                     {orj, oij, ojj, ojk},
                     {ork, oik, ojk, okk}};

    float g0 = gamma[0 * CH + c], g1 = gamma[1 * CH + c], g2 = gamma[2 * CH + c];
    float g3 = gamma[3 * CH + c], g4 = gamma[4 * CH + c], g5 = gamma[5 * CH + c];
    float g6 = gamma[6 * CH + c], g7 = gamma[7 * CH + c], g8 = gamma[8 * CH + c];
    float g9 = gamma[9 * CH + c];
    float G[4][4] = {{g0, g1, g2, g3},
                     {g1, g4, g5, g6},
                     {g2, g5, g7, g8},
                     {g3, g6, g8, g9}};

#pragma unroll
    for (int p = 0; p < 4; ++p) {
#pragma unroll
        for (int s = 0; s < 4; ++s) {
            float acc = 0.f;
#pragma unroll
            for (int q = 0; q < 4; ++q) acc += G[p][q] * W[q][s];
            g_M[(p * 4 + s) * CH + c] = acc;
        }
        g_mu[p * CH + c] = mu[p];
    }
}

// ---------------------------------------------------------------------------
// Kernel 3: apply out[p] = M[p][q] * (x[q]-mu[q]) + beta[p].
// float4 over channels (64 groups), 4 rows per block iteration, M/mu/beta in
// shared memory (24 KB). Grid-stride over rows.
// ---------------------------------------------------------------------------
__global__ void __launch_bounds__(256) k_apply(const float* __restrict__ x,
                                               const float* __restrict__ beta,
                                               float* __restrict__ out, int S) {
    __shared__ float4 sM[16 * 64];
    __shared__ float4 sMu[4 * 64];
    __shared__ float4 sB[4 * 64];

    const int t = threadIdx.x;
    const float4* gM4 = (const float4*)g_M;
    for (int i = t; i < 16 * 64; i += 256) sM[i] = gM4[i];
    if (t < 4 * 64) {
        sMu[t] = ((const float4*)g_mu)[t];
        sB[t] = ((const float4*)beta)[t];
    }
    __syncthreads();

    const int g = t & 63;   // channel quad
    const int rq = t >> 6;  // row within quad (0..3)

    float4 mu[4], bt[4];
#pragma unroll
    for (int p = 0; p < 4; ++p) {
        mu[p] = sMu[p * 64 + g];
        bt[p] = sB[p * 64 + g];
    }

    const long long CS = (long long)S * CH;
    const long long stride = (long long)gridDim.x * 4;

    for (long long s = (long long)blockIdx.x * 4 + rq; s < S; s += stride) {
        long long base = s * CH + g * 4;
        float4 xc[4];
        xc[0] = *(const float4*)(x + base);
        xc[1] = *(const float4*)(x + CS + base);
        xc[2] = *(const float4*)(x + 2 * CS + base);
        xc[3] = *(const float4*)(x + 3 * CS + base);
#pragma unroll
        for (int q = 0; q < 4; ++q) {
            xc[q].x -= mu[q].x; xc[q].y -= mu[q].y;
            xc[q].z -= mu[q].z; xc[q].w -= mu[q].w;
        }
#pragma unroll
        for (int p = 0; p < 4; ++p) {
            float4 o = bt[p];
#pragma unroll
            for (int q = 0; q < 4; ++q) {
                float4 m = sM[(p * 4 + q) * 64 + g];
                o.x += m.x * xc[q].x;
                o.y += m.y * xc[q].y;
                o.z += m.z * xc[q].z;
                o.w += m.w * xc[q].w;
            }
            *(float4*)(out + p * CS + base) = o;
        }
    }
}

// ---------------------------------------------------------------------------
extern "C" void kernel_launch(void* const* d_in, const int* in_sizes, int n_in,
                              void* d_out, int out_size) {
    const float* x = (const float*)d_in[0];
    const float* gamma = (const float*)d_in[1];
    const float* beta = (const float*)d_in[2];
    float* out = (float*)d_out;

    const int S = in_sizes[0] / (4 * CH);  // spatial rows per component (B*H*W)

    k_zero<<<14, 256>>>();

    const int rBlocks = 1024;
    const int rowsPerBlock = (S + rBlocks - 1) / rBlocks;
    k_reduce<<<rBlocks, CH>>>(x, S, rowsPerBlock);

    k_stats<<<1, CH>>>(gamma, S);

    k_apply<<<2048, 256>>>(x, beta, out, S);
}

// round 2
// speedup vs baseline: 1.0421x; 1.0421x over previous
#include <cuda_runtime.h>

#define CH 256
#define QEPS 1e-4f

// Scratch (no allocations allowed).
__device__ float g_sums[14 * CH];
__device__ float g_M[16 * CH];
__device__ float g_bias[4 * CH];   // beta - M @ mu  (folded bias)

// ---------------------------------------------------------------------------
// Kernel 0: zero the reduction scratch (graph replays must be deterministic).
// ---------------------------------------------------------------------------
__global__ void k_zero() {
    int i = blockIdx.x * blockDim.x + threadIdx.x;
    if (i < 14 * CH) g_sums[i] = 0.0f;
}

// ---------------------------------------------------------------------------
// Kernel 1: per-channel sums and product-sums.
// thread c = channel, block covers rowsPerBlock consecutive spatial rows.
// Coalesced 32-bit loads, 14 register accumulators, 14 atomicAdds at end.
// ---------------------------------------------------------------------------
__global__ void __launch_bounds__(CH) k_reduce(const float* __restrict__ x,
                                               int S, int rowsPerBlock) {
    const int c = threadIdx.x;
    int s0 = blockIdx.x * rowsPerBlock;
    if (s0 >= S) return;
    int nrows = rowsPerBlock;
    if (s0 + nrows > S) nrows = S - s0;

    const unsigned CS = (unsigned)S * CH;
    const float* b = x + (unsigned)s0 * CH + c;

    float sm0 = 0.f, sm1 = 0.f, sm2 = 0.f, sm3 = 0.f;
    float p00 = 0.f, p01 = 0.f, p02 = 0.f, p03 = 0.f;
    float p11 = 0.f, p12 = 0.f, p13 = 0.f;
    float p22 = 0.f, p23 = 0.f, p33 = 0.f;

#pragma unroll 4
    for (int r = 0; r < nrows; ++r) {
        unsigned off = (unsigned)r * CH;
        float x0 = __ldg(b + off);
        float x1 = __ldg(b + CS + off);
        float x2 = __ldg(b + 2 * CS + off);
        float x3 = __ldg(b + 3 * CS + off);
        sm0 += x0; sm1 += x1; sm2 += x2; sm3 += x3;
        p00 += x0 * x0; p01 += x0 * x1; p02 += x0 * x2; p03 += x0 * x3;
        p11 += x1 * x1; p12 += x1 * x2; p13 += x1 * x3;
        p22 += x2 * x2; p23 += x2 * x3;
        p33 += x3 * x3;
    }

    atomicAdd(&g_sums[0 * CH + c], sm0);
    atomicAdd(&g_sums[1 * CH + c], sm1);
    atomicAdd(&g_sums[2 * CH + c], sm2);
    atomicAdd(&g_sums[3 * CH + c], sm3);
    atomicAdd(&g_sums[4 * CH + c], p00);   // rr
    atomicAdd(&g_sums[5 * CH + c], p01);   // ri
    atomicAdd(&g_sums[6 * CH + c], p02);   // rj
    atomicAdd(&g_sums[7 * CH + c], p03);   // rk
    atomicAdd(&g_sums[8 * CH + c], p11);   // ii
    atomicAdd(&g_sums[9 * CH + c], p12);   // ij
    atomicAdd(&g_sums[10 * CH + c], p13);  // ik
    atomicAdd(&g_sums[11 * CH + c], p22);  // jj
    atomicAdd(&g_sums[12 * CH + c], p23);  // jk
    atomicAdd(&g_sums[13 * CH + c], p33);  // kk
}

// ---------------------------------------------------------------------------
// Kernel 2: stats -> whitening -> M = G @ W, and folded bias = beta - M @ mu.
// One block, thread = channel. Mirrors _whitening_matrix exactly.
// ---------------------------------------------------------------------------
__global__ void k_stats(const float* __restrict__ gamma,
                        const float* __restrict__ beta, int S) {
    const int c = threadIdx.x;
    const float invN = 1.0f / (float)S;

    float mu[4];
#pragma unroll
    for (int p = 0; p < 4; ++p) mu[p] = g_sums[p * CH + c] * invN;

    // cov entries: 0 rr,1 ri,2 rj,3 rk,4 ii,5 ij,6 ik,7 jj,8 jk,9 kk
    const int ta[10] = {0, 0, 0, 0, 1, 1, 1, 2, 2, 3};
    const int tb[10] = {0, 1, 2, 3, 1, 2, 3, 2, 3, 3};
    float v[10];
#pragma unroll
    for (int i = 0; i < 10; ++i) {
        v[i] = g_sums[(4 + i) * CH + c] * invN - mu[ta[i]] * mu[tb[i]];
        if (ta[i] == tb[i]) v[i] += QEPS;
    }

    float wrr = sqrtf(v[0]);
    float wri = v[1] / wrr;
    float wii = sqrtf(v[4] - wri * wri);
    float wrj = v[2] / wrr;
    float wij = (v[5] - wri * wrj) / wii;
    float wjj = sqrtf(v[7] - (wij * wij + wrj * wrj));
    float wrk = v[3] / wrr;
    float wik = (v[6] - wri * wrk) / wii;
    float wjk = (v[8] - (wij * wik + wrj * wrk)) / wjj;
    float wkk = sqrtf(v[9] - (wjk * wjk + wik * wik + wrk * wrk));

    float orr = 1.0f / wrr, oii = 1.0f / wii, ojj = 1.0f / wjj, okk = 1.0f / wkk;
    float ori = -(wri * orr) / wii;
    float orj = -(wrj * orr + wij * ori) / wjj;
    float ork = -(wrk * orr + wik * ori + wjk * orj) / wkk;
    float oij = -(wij * oii) / wjj;
    float oik = -(wik * oii + wjk * oij) / wkk;
    float ojk = -(wjk * ojj) / wkk;

    float W[4][4] = {{orr, ori, orj, ork},
                     {ori, oii, oij, oik},
                     {orj, oij, ojj, ojk},
                     {ork, oik, ojk, okk}};

    float g0 = gamma[0 * CH + c], g1 = gamma[1 * CH + c], g2 = gamma[2 * CH + c];
    float g3 = gamma[3 * CH + c], g4 = gamma[4 * CH + c], g5 = gamma[5 * CH + c];
    float g6 = gamma[6 * CH + c], g7 = gamma[7 * CH + c], g8 = gamma[8 * CH + c];
    float g9 = gamma[9 * CH + c];
    float G[4][4] = {{g0, g1, g2, g3},
                     {g1, g4, g5, g6},
                     {g2, g5, g7, g8},
                     {g3, g6, g8, g9}};

#pragma unroll
    for (int p = 0; p < 4; ++p) {
        float bias = beta[p * CH + c];
#pragma unroll
        for (int s = 0; s < 4; ++s) {
            float acc = 0.f;
#pragma unroll
            for (int q = 0; q < 4; ++q) acc += G[p][q] * W[q][s];
            g_M[(p * 4 + s) * CH + c] = acc;
            bias -= acc * mu[s];   // fold mean: bias' = beta - M @ mu
        }
        g_bias[p * CH + c] = bias;
    }
}

// ---------------------------------------------------------------------------
// Kernel 3: out[p] = sum_q M[p][q] * x[q] + bias'[p].
// float4 over channels (64 quads), 4 rows per block iteration, M/bias in
// shared. launch_bounds(256,3) keeps regs <=85 -> 24 warps/SM (3x occupancy).
// ---------------------------------------------------------------------------
__global__ void __launch_bounds__(256, 3) k_apply(const float* __restrict__ x,
                                                  float* __restrict__ out, int S) {
    __shared__ float4 sM[16 * 64];
    __shared__ float4 sB[4 * 64];

    const int t = threadIdx.x;
    const float4* gM4 = (const float4*)g_M;
    for (int i = t; i < 16 * 64; i += 256) sM[i] = gM4[i];
    sB[t] = ((const float4*)g_bias)[t];   // exactly 256 entries
    __syncthreads();

    const int g = t & 63;    // channel quad
    const int rq = t >> 6;   // row within quad (0..3)

    const unsigned CS = (unsigned)S * CH;
    const unsigned stride = (unsigned)gridDim.x * 4u;

    for (unsigned s = (unsigned)blockIdx.x * 4u + rq; s < (unsigned)S; s += stride) {
        unsigned base = s * CH + (unsigned)g * 4u;
        float4 x0 = *(const float4*)(x + base);
        float4 x1 = *(const float4*)(x + CS + base);
        float4 x2 = *(const float4*)(x + 2 * CS + base);
        float4 x3 = *(const float4*)(x + 3 * CS + base);
#pragma unroll
        for (int p = 0; p < 4; ++p) {
            float4 o = sB[p * 64 + g];
            float4 m;
            m = sM[(p * 4 + 0) * 64 + g];
            o.x += m.x * x0.x; o.y += m.y * x0.y; o.z += m.z * x0.z; o.w += m.w * x0.w;
            m = sM[(p * 4 + 1) * 64 + g];
            o.x += m.x * x1.x; o.y += m.y * x1.y; o.z += m.z * x1.z; o.w += m.w * x1.w;
            m = sM[(p * 4 + 2) * 64 + g];
            o.x += m.x * x2.x; o.y += m.y * x2.y; o.z += m.z * x2.z; o.w += m.w * x2.w;
            m = sM[(p * 4 + 3) * 64 + g];
            o.x += m.x * x3.x; o.y += m.y * x3.y; o.z += m.z * x3.z; o.w += m.w * x3.w;
            *(float4*)(out + p * CS + base) = o;
        }
    }
}

// ---------------------------------------------------------------------------
extern "C" void kernel_launch(void* const* d_in, const int* in_sizes, int n_in,
                              void* d_out, int out_size) {
    const float* x = (const float*)d_in[0];
    const float* gamma = (const float*)d_in[1];
    const float* beta = (const float*)d_in[2];
    float* out = (float*)d_out;

    const int S = in_sizes[0] / (4 * CH);  // spatial rows per component (B*H*W)

    k_zero<<<14, 256>>>();

    const int rBlocks = 1024;
    const int rowsPerBlock = (S + rBlocks - 1) / rBlocks;
    k_reduce<<<rBlocks, CH>>>(x, S, rowsPerBlock);

    k_stats<<<1, CH>>>(gamma, beta, S);

    k_apply<<<2048, 256>>>(x, out, S);
}

// round 3
// speedup vs baseline: 1.2393x; 1.1892x over previous
#include <cuda_runtime.h>

#define CH 256
#define QEPS 1e-4f
#define RBLOCKS 592

// Scratch (no allocations allowed).
__device__ float g_sums[14 * CH];
__device__ float g_M[16 * CH];
__device__ float g_bias[4 * CH];   // beta - M @ mu  (folded bias)

// ---------------------------------------------------------------------------
// Kernel 0: zero the reduction scratch (graph replays must be deterministic).
// ---------------------------------------------------------------------------
__global__ void k_zero() {
    int i = blockIdx.x * blockDim.x + threadIdx.x;
    if (i < 14 * CH) g_sums[i] = 0.0f;
}

// ---------------------------------------------------------------------------
// Kernel 1: per-channel sums and product-sums, float4 over channels.
// thread: channel quad g = t&63, row phase rq = t>>6 (4 rows per step).
// 14 float4 register accumulators; smem block-reduce over the 4 row-threads,
// then 64 threads do 4 atomicAdds each per accumulator.
// ---------------------------------------------------------------------------
__global__ void __launch_bounds__(256, 2) k_reduce(const float* __restrict__ x,
                                                   int S, int rowsPerBlock) {
    const int t = threadIdx.x;
    const int g = t & 63;
    const int rq = t >> 6;

    int s0 = blockIdx.x * rowsPerBlock;
    int send = s0 + rowsPerBlock;
    if (send > S) send = S;

    const unsigned CS = (unsigned)S * CH;

    float4 a[14];
#pragma unroll
    for (int i = 0; i < 14; ++i) a[i] = make_float4(0.f, 0.f, 0.f, 0.f);

#pragma unroll 2
    for (int s = s0 + rq; s < send; s += 4) {
        unsigned base = (unsigned)s * CH + (unsigned)g * 4u;
        float4 x0 = __ldg((const float4*)(x + base));
        float4 x1 = __ldg((const float4*)(x + CS + base));
        float4 x2 = __ldg((const float4*)(x + 2 * CS + base));
        float4 x3 = __ldg((const float4*)(x + 3 * CS + base));

        a[0].x += x0.x; a[0].y += x0.y; a[0].z += x0.z; a[0].w += x0.w;
        a[1].x += x1.x; a[1].y += x1.y; a[1].z += x1.z; a[1].w += x1.w;
        a[2].x += x2.x; a[2].y += x2.y; a[2].z += x2.z; a[2].w += x2.w;
        a[3].x += x3.x; a[3].y += x3.y; a[3].z += x3.z; a[3].w += x3.w;

        a[4].x += x0.x * x0.x; a[4].y += x0.y * x0.y; a[4].z += x0.z * x0.z; a[4].w += x0.w * x0.w;   // rr
        a[5].x += x0.x * x1.x; a[5].y += x0.y * x1.y; a[5].z += x0.z * x1.z; a[5].w += x0.w * x1.w;   // ri
        a[6].x += x0.x * x2.x; a[6].y += x0.y * x2.y; a[6].z += x0.z * x2.z; a[6].w += x0.w * x2.w;   // rj
        a[7].x += x0.x * x3.x; a[7].y += x0.y * x3.y; a[7].z += x0.z * x3.z; a[7].w += x0.w * x3.w;   // rk
        a[8].x += x1.x * x1.x; a[8].y += x1.y * x1.y; a[8].z += x1.z * x1.z; a[8].w += x1.w * x1.w;   // ii
        a[9].x += x1.x * x2.x; a[9].y += x1.y * x2.y; a[9].z += x1.z * x2.z; a[9].w += x1.w * x2.w;   // ij
        a[10].x += x1.x * x3.x; a[10].y += x1.y * x3.y; a[10].z += x1.z * x3.z; a[10].w += x1.w * x3.w; // ik
        a[11].x += x2.x * x2.x; a[11].y += x2.y * x2.y; a[11].z += x2.z * x2.z; a[11].w += x2.w * x2.w; // jj
        a[12].x += x2.x * x3.x; a[12].y += x2.y * x3.y; a[12].z += x2.z * x3.z; a[12].w += x2.w * x3.w; // jk
        a[13].x += x3.x * x3.x; a[13].y += x3.y * x3.y; a[13].z += x3.z * x3.z; a[13].w += x3.w * x3.w; // kk
    }

    __shared__ float4 red[256];
#pragma unroll
    for (int i = 0; i < 14; ++i) {
        red[t] = a[i];
        __syncthreads();
        if (t < 64) {
            float4 v = red[t];
            float4 v1 = red[t + 64], v2 = red[t + 128], v3 = red[t + 192];
            v.x += v1.x + v2.x + v3.x;
            v.y += v1.y + v2.y + v3.y;
            v.z += v1.z + v2.z + v3.z;
            v.w += v1.w + v2.w + v3.w;
            float* dst = &g_sums[i * CH + t * 4];
            atomicAdd(dst + 0, v.x);
            atomicAdd(dst + 1, v.y);
            atomicAdd(dst + 2, v.z);
            atomicAdd(dst + 3, v.w);
        }
        __syncthreads();
    }
}

// ---------------------------------------------------------------------------
// Kernel 2: stats -> whitening -> M = G @ W, and folded bias = beta - M @ mu.
// One block, thread = channel. Mirrors _whitening_matrix exactly.
// ---------------------------------------------------------------------------
__global__ void k_stats(const float* __restrict__ gamma,
                        const float* __restrict__ beta, int S) {
    const int c = threadIdx.x;
    const float invN = 1.0f / (float)S;

    float mu[4];
#pragma unroll
    for (int p = 0; p < 4; ++p) mu[p] = g_sums[p * CH + c] * invN;

    // cov entries: 0 rr,1 ri,2 rj,3 rk,4 ii,5 ij,6 ik,7 jj,8 jk,9 kk
    const int ta[10] = {0, 0, 0, 0, 1, 1, 1, 2, 2, 3};
    const int tb[10] = {0, 1, 2, 3, 1, 2, 3, 2, 3, 3};
    float v[10];
#pragma unroll
    for (int i = 0; i < 10; ++i) {
        v[i] = g_sums[(4 + i) * CH + c] * invN - mu[ta[i]] * mu[tb[i]];
        if (ta[i] == tb[i]) v[i] += QEPS;
    }

    float wrr = sqrtf(v[0]);
    float wri = v[1] / wrr;
    float wii = sqrtf(v[4] - wri * wri);
    float wrj = v[2] / wrr;
    float wij = (v[5] - wri * wrj) / wii;
    float wjj = sqrtf(v[7] - (wij * wij + wrj * wrj));
    float wrk = v[3] / wrr;
    float wik = (v[6] - wri * wrk) / wii;
    float wjk = (v[8] - (wij * wik + wrj * wrk)) / wjj;
    float wkk = sqrtf(v[9] - (wjk * wjk + wik * wik + wrk * wrk));

    float orr = 1.0f / wrr, oii = 1.0f / wii, ojj = 1.0f / wjj, okk = 1.0f / wkk;
    float ori = -(wri * orr) / wii;
    float orj = -(wrj * orr + wij * ori) / wjj;
    float ork = -(wrk * orr + wik * ori + wjk * orj) / wkk;
    float oij = -(wij * oii) / wjj;
    float oik = -(wik * oii + wjk * oij) / wkk;
    float ojk = -(wjk * ojj) / wkk;

    float W[4][4] = {{orr, ori, orj, ork},
                     {ori, oii, oij, oik},
                     {orj, oij, ojj, ojk},
                     {ork, oik, ojk, okk}};

    float g0 = gamma[0 * CH + c], g1 = gamma[1 * CH + c], g2 = gamma[2 * CH + c];
    float g3 = gamma[3 * CH + c], g4 = gamma[4 * CH + c], g5 = gamma[5 * CH + c];
    float g6 = gamma[6 * CH + c], g7 = gamma[7 * CH + c], g8 = gamma[8 * CH + c];
    float g9 = gamma[9 * CH + c];
    float G[4][4] = {{g0, g1, g2, g3},
                     {g1, g4, g5, g6},
                     {g2, g5, g7, g8},
                     {g3, g6, g8, g9}};

#pragma unroll
    for (int p = 0; p < 4; ++p) {
        float bias = beta[p * CH + c];
#pragma unroll
        for (int s = 0; s < 4; ++s) {
            float acc = 0.f;
#pragma unroll
            for (int q = 0; q < 4; ++q) acc += G[p][q] * W[q][s];
            g_M[(p * 4 + s) * CH + c] = acc;
            bias -= acc * mu[s];   // fold mean: bias' = beta - M @ mu
        }
        g_bias[p * CH + c] = bias;
    }
}

// ---------------------------------------------------------------------------
// Kernel 3: out[p] = sum_q M[p][q] * x[q] + bias'[p].
// float2 over channels (128 pairs), M + bias fully register-resident and
// loop-invariant -> zero shared-memory traffic in the hot loop.
// launch_bounds(256,4): ~60 regs, 32 warps/SM (occ 50%).
// ---------------------------------------------------------------------------
__global__ void __launch_bounds__(256, 4) k_apply(const float* __restrict__ x,
                                                  float* __restrict__ out, int S) {
    const int t = threadIdx.x;
    const int g = t & 127;   // channel pair index (c = 2g, 2g+1)
    const int rq = t >> 7;   // row within pair (0..1)

    const float2* M2 = (const float2*)g_M;
    const float2* B2 = (const float2*)g_bias;

    float2 m[16], b[4];
#pragma unroll
    for (int i = 0; i < 16; ++i) m[i] = M2[i * 128 + g];
#pragma unroll
    for (int p = 0; p < 4; ++p) b[p] = B2[p * 128 + g];

    const unsigned CS = (unsigned)S * CH;
    const unsigned stride = (unsigned)gridDim.x * 2u;

    for (unsigned s = (unsigned)blockIdx.x * 2u + rq; s < (unsigned)S; s += stride) {
        unsigned base = s * CH + (unsigned)g * 2u;
        float2 x0 = __ldg((const float2*)(x + base));
        float2 x1 = __ldg((const float2*)(x + CS + base));
        float2 x2 = __ldg((const float2*)(x + 2 * CS + base));
        float2 x3 = __ldg((const float2*)(x + 3 * CS + base));
#pragma unroll
        for (int p = 0; p < 4; ++p) {
            float2 o = b[p];
            o.x += m[p * 4 + 0].x * x0.x; o.y += m[p * 4 + 0].y * x0.y;
            o.x += m[p * 4 + 1].x * x1.x; o.y += m[p * 4 + 1].y * x1.y;
            o.x += m[p * 4 + 2].x * x2.x; o.y += m[p * 4 + 2].y * x2.y;
            o.x += m[p * 4 + 3].x * x3.x; o.y += m[p * 4 + 3].y * x3.y;
            *(float2*)(out + p * CS + base) = o;
        }
    }
}

// ---------------------------------------------------------------------------
extern "C" void kernel_launch(void* const* d_in, const int* in_sizes, int n_in,
                              void* d_out, int out_size) {
    const float* x = (const float*)d_in[0];
    const float* gamma = (const float*)d_in[1];
    const float* beta = (const float*)d_in[2];
    float* out = (float*)d_out;

    const int S = in_sizes[0] / (4 * CH);  // spatial rows per component (B*H*W)

    k_zero<<<14, 256>>>();

    const int rowsPerBlock = (S + RBLOCKS - 1) / RBLOCKS;
    k_reduce<<<RBLOCKS, 256>>>(x, S, rowsPerBlock);

    k_stats<<<1, CH>>>(gamma, beta, S);

    k_apply<<<2048, 256>>>(x, out, S);
}

// round 4
// speedup vs baseline: 1.3630x; 1.0998x over previous
#include <cuda_runtime.h>

#define CH 256
#define QEPS 1e-4f
#define RBLOCKS 444   // 3 per SM * 148
#define ABLOCKS 444

// Scratch (no allocations allowed).
__device__ float g_sums[14 * CH];
__device__ float g_M[16 * CH];
__device__ float g_bias[4 * CH];   // beta - M @ mu  (folded bias)

// ---------------------------------------------------------------------------
// Kernel 0: zero the reduction scratch (graph replays must be deterministic).
// ---------------------------------------------------------------------------
__global__ void k_zero() {
    int i = blockIdx.x * blockDim.x + threadIdx.x;
    if (i < 14 * CH) g_sums[i] = 0.0f;
}

// ---------------------------------------------------------------------------
// Kernel 1: per-channel sums and product-sums, float2 over channels.
// thread: channel pair g = t&127, row phase rq = t>>7 (2 rows per step).
// 14 float2 register accumulators (28 regs) -> 3 blocks/SM.
// smem block-reduce over the 2 row-phase threads, then atomics.
// ---------------------------------------------------------------------------
__global__ void __launch_bounds__(256, 3) k_reduce(const float* __restrict__ x,
                                                   int S, int rowsPerBlock) {
    const int t = threadIdx.x;
    const int g = t & 127;
    const int rq = t >> 7;

    int s0 = blockIdx.x * rowsPerBlock;
    int send = s0 + rowsPerBlock;
    if (send > S) send = S;

    const unsigned CS = (unsigned)S * CH;

    float2 a[14];
#pragma unroll
    for (int i = 0; i < 14; ++i) a[i] = make_float2(0.f, 0.f);

#pragma unroll 4
    for (int s = s0 + rq; s < send; s += 2) {
        unsigned base = (unsigned)s * CH + (unsigned)g * 2u;
        float2 x0 = __ldcs((const float2*)(x + base));
        float2 x1 = __ldcs((const float2*)(x + CS + base));
        float2 x2 = __ldcs((const float2*)(x + 2 * CS + base));
        float2 x3 = __ldcs((const float2*)(x + 3 * CS + base));

        a[0].x += x0.x;        a[0].y += x0.y;
        a[1].x += x1.x;        a[1].y += x1.y;
        a[2].x += x2.x;        a[2].y += x2.y;
        a[3].x += x3.x;        a[3].y += x3.y;
        a[4].x += x0.x * x0.x; a[4].y += x0.y * x0.y;   // rr
        a[5].x += x0.x * x1.x; a[5].y += x0.y * x1.y;   // ri
        a[6].x += x0.x * x2.x; a[6].y += x0.y * x2.y;   // rj
        a[7].x += x0.x * x3.x; a[7].y += x0.y * x3.y;   // rk
        a[8].x += x1.x * x1.x; a[8].y += x1.y * x1.y;   // ii
        a[9].x += x1.x * x2.x; a[9].y += x1.y * x2.y;   // ij
        a[10].x += x1.x * x3.x; a[10].y += x1.y * x3.y; // ik
        a[11].x += x2.x * x2.x; a[11].y += x2.y * x2.y; // jj
        a[12].x += x2.x * x3.x; a[12].y += x2.y * x3.y; // jk
        a[13].x += x3.x * x3.x; a[13].y += x3.y * x3.y; // kk
    }

    __shared__ float2 red[512];
    // stage two accumulators per pass to halve the sync count
#pragma unroll
    for (int i = 0; i < 14; i += 2) {
        red[t] = a[i];
        red[256 + t] = a[i + 1];
        __syncthreads();
        if (t < 128) {
            float2 v = red[t], w = red[t + 128];
            v.x += w.x; v.y += w.y;
            float* dst = &g_sums[i * CH + t * 2];
            atomicAdd(dst + 0, v.x);
            atomicAdd(dst + 1, v.y);
            v = red[256 + t]; w = red[256 + t + 128];
            v.x += w.x; v.y += w.y;
            dst = &g_sums[(i + 1) * CH + t * 2];
            atomicAdd(dst + 0, v.x);
            atomicAdd(dst + 1, v.y);
        }
        __syncthreads();
    }
}

// ---------------------------------------------------------------------------
// Kernel 2: stats -> whitening -> M = G @ W, and folded bias = beta - M @ mu.
// One block, thread = channel. Mirrors _whitening_matrix exactly.
// ---------------------------------------------------------------------------
__global__ void k_stats(const float* __restrict__ gamma,
                        const float* __restrict__ beta, int S) {
    const int c = threadIdx.x;
    const float invN = 1.0f / (float)S;

    float mu[4];
#pragma unroll
    for (int p = 0; p < 4; ++p) mu[p] = g_sums[p * CH + c] * invN;

    // cov entries: 0 rr,1 ri,2 rj,3 rk,4 ii,5 ij,6 ik,7 jj,8 jk,9 kk
    const int ta[10] = {0, 0, 0, 0, 1, 1, 1, 2, 2, 3};
    const int tb[10] = {0, 1, 2, 3, 1, 2, 3, 2, 3, 3};
    float v[10];
#pragma unroll
    for (int i = 0; i < 10; ++i) {
        v[i] = g_sums[(4 + i) * CH + c] * invN - mu[ta[i]] * mu[tb[i]];
        if (ta[i] == tb[i]) v[i] += QEPS;
    }

    float wrr = sqrtf(v[0]);
    float wri = v[1] / wrr;
    float wii = sqrtf(v[4] - wri * wri);
    float wrj = v[2] / wrr;
    float wij = (v[5] - wri * wrj) / wii;
    float wjj = sqrtf(v[7] - (wij * wij + wrj * wrj));
    float wrk = v[3] / wrr;
    float wik = (v[6] - wri * wrk) / wii;
    float wjk = (v[8] - (wij * wik + wrj * wrk)) / wjj;
    float wkk = sqrtf(v[9] - (wjk * wjk + wik * wik + wrk * wrk));

    float orr = 1.0f / wrr, oii = 1.0f / wii, ojj = 1.0f / wjj, okk = 1.0f / wkk;
    float ori = -(wri * orr) / wii;
    float orj = -(wrj * orr + wij * ori) / wjj;
    float ork = -(wrk * orr + wik * ori + wjk * orj) / wkk;
    float oij = -(wij * oii) / wjj;
    float oik = -(wik * oii + wjk * oij) / wkk;
    float ojk = -(wjk * ojj) / wkk;

    float W[4][4] = {{orr, ori, orj, ork},
                     {ori, oii, oij, oik},
                     {orj, oij, ojj, ojk},
                     {ork, oik, ojk, okk}};

    float g0 = gamma[0 * CH + c], g1 = gamma[1 * CH + c], g2 = gamma[2 * CH + c];
    float g3 = gamma[3 * CH + c], g4 = gamma[4 * CH + c], g5 = gamma[5 * CH + c];
    float g6 = gamma[6 * CH + c], g7 = gamma[7 * CH + c], g8 = gamma[8 * CH + c];
    float g9 = gamma[9 * CH + c];
    float G[4][4] = {{g0, g1, g2, g3},
                     {g1, g4, g5, g6},
                     {g2, g5, g7, g8},
                     {g3, g6, g8, g9}};

#pragma unroll
    for (int p = 0; p < 4; ++p) {
        float bias = beta[p * CH + c];
#pragma unroll
        for (int s = 0; s < 4; ++s) {
            float acc = 0.f;
#pragma unroll
            for (int q = 0; q < 4; ++q) acc += G[p][q] * W[q][s];
            g_M[(p * 4 + s) * CH + c] = acc;
            bias -= acc * mu[s];   // fold mean: bias' = beta - M @ mu
        }
        g_bias[p * CH + c] = bias;
    }
}

// ---------------------------------------------------------------------------
// Kernel 3: out[p] = sum_q M[p][q] * x[q] + bias'[p].
// float2 over channels, M + bias register-resident, 2 spatial rows per
// iteration (8 outstanding LDG.64 per thread). Persistent grid-stride,
// streaming cache hints (zero reuse). launch_bounds(256,3) -> 24 warps/SM.
// ---------------------------------------------------------------------------
__global__ void __launch_bounds__(256, 3) k_apply(const float* __restrict__ x,
                                                  float* __restrict__ out, int S) {
    const int t = threadIdx.x;
    const int g = t & 127;   // channel pair index
    const int rq = t >> 7;   // row phase (0..1)

    const float2* M2 = (const float2*)g_M;
    const float2* B2 = (const float2*)g_bias;

    float2 m[16], b[4];
#pragma unroll
    for (int i = 0; i < 16; ++i) m[i] = M2[i * 128 + g];
#pragma unroll
    for (int p = 0; p < 4; ++p) b[p] = B2[p * 128 + g];

    const unsigned CS = (unsigned)S * CH;
    const unsigned stride = (unsigned)gridDim.x * 4u;   // 4 rows per block-iter
    const unsigned Sv = (unsigned)S & ~3u;              // multiple-of-4 body

    unsigned s = (unsigned)blockIdx.x * 4u + rq;
    for (; s + 2 < Sv; s += stride) {
        unsigned bA = s * CH + (unsigned)g * 2u;
        unsigned bB = bA + 2u * CH;                     // row s+2
        float2 xA0 = __ldcs((const float2*)(x + bA));
        float2 xB0 = __ldcs((const float2*)(x + bB));
        float2 xA1 = __ldcs((const float2*)(x + CS + bA));
        float2 xB1 = __ldcs((const float2*)(x + CS + bB));
        float2 xA2 = __ldcs((const float2*)(x + 2 * CS + bA));
        float2 xB2 = __ldcs((const float2*)(x + 2 * CS + bB));
        float2 xA3 = __ldcs((const float2*)(x + 3 * CS + bA));
        float2 xB3 = __ldcs((const float2*)(x + 3 * CS + bB));
#pragma unroll
        for (int p = 0; p < 4; ++p) {
            float2 oA = b[p], oB = b[p];
            oA.x += m[p * 4 + 0].x * xA0.x; oA.y += m[p * 4 + 0].y * xA0.y;
            oB.x += m[p * 4 + 0].x * xB0.x; oB.y += m[p * 4 + 0].y * xB0.y;
            oA.x += m[p * 4 + 1].x * xA1.x; oA.y += m[p * 4 + 1].y * xA1.y;
            oB.x += m[p * 4 + 1].x * xB1.x; oB.y += m[p * 4 + 1].y * xB1.y;
            oA.x += m[p * 4 + 2].x * xA2.x; oA.y += m[p * 4 + 2].y * xA2.y;
            oB.x += m[p * 4 + 2].x * xB2.x; oB.y += m[p * 4 + 2].y * xB2.y;
            oA.x += m[p * 4 + 3].x * xA3.x; oA.y += m[p * 4 + 3].y * xA3.y;
            oB.x += m[p * 4 + 3].x * xB3.x; oB.y += m[p * 4 + 3].y * xB3.y;
            __stcs((float2*)(out + p * CS + bA), oA);
            __stcs((float2*)(out + p * CS + bB), oB);
        }
    }
    // tail (also covers the residual rows when S % 4 != 0)
    for (; s < (unsigned)S; s += 2u) {
        unsigned base = s * CH + (unsigned)g * 2u;
        float2 x0 = __ldcs((const float2*)(x + base));
        float2 x1 = __ldcs((const float2*)(x + CS + base));
        float2 x2 = __ldcs((const float2*)(x + 2 * CS + base));
        float2 x3 = __ldcs((const float2*)(x + 3 * CS + base));
#pragma unroll
        for (int p = 0; p < 4; ++p) {
            float2 o = b[p];
            o.x += m[p * 4 + 0].x * x0.x; o.y += m[p * 4 + 0].y * x0.y;
            o.x += m[p * 4 + 1].x * x1.x; o.y += m[p * 4 + 1].y * x1.y;
            o.x += m[p * 4 + 2].x * x2.x; o.y += m[p * 4 + 2].y * x2.y;
            o.x += m[p * 4 + 3].x * x3.x; o.y += m[p * 4 + 3].y * x3.y;
            __stcs((float2*)(out + p * CS + base), o);
        }
    }
}

// ---------------------------------------------------------------------------
extern "C" void kernel_launch(void* const* d_in, const int* in_sizes, int n_in,
                              void* d_out, int out_size) {
    const float* x = (const float*)d_in[0];
    const float* gamma = (const float*)d_in[1];
    const float* beta = (const float*)d_in[2];
    float* out = (float*)d_out;

    const int S = in_sizes[0] / (4 * CH);  // spatial rows per component (B*H*W)

    k_zero<<<14, 256>>>();

    const int rowsPerBlock = (S + RBLOCKS - 1) / RBLOCKS;
    k_reduce<<<RBLOCKS, 256>>>(x, S, rowsPerBlock);

    k_stats<<<1, CH>>>(gamma, beta, S);

    k_apply<<<ABLOCKS, 256>>>(x, out, S);
}